// round 5
// baseline (speedup 1.0000x reference)
#include <cuda_runtime.h>
#include <cuda_bf16.h>
#include <math_constants.h>

#define FULL 0xffffffffu

static constexpr int B = 8;
static constexpr int N = 4096;
static constexpr int C = 128;
static constexpr int KNN = 16;

// scratch (device globals: no allocation allowed)
__device__ float  g_zbn[B * N * C];     // zbn[b][n][c], n-major rows of 512B
__device__ float4 g_xyz4[B * N];        // (x,y,z,|p|^2) original order
__device__ int    g_idx[B * N * KNN];   // 16 NN orig indices per query
__device__ unsigned long long g_key[B * N];  // (r_bits<<32)|loc, per batch
__device__ float4 g_srt[B * N];         // points sorted by radius
__device__ int    g_sorig[B * N];       // sorted rank -> orig index

// ---------------------------------------------------------------------------
// Kernel 0: pack xyz + squared norm + radius sort key
// ---------------------------------------------------------------------------
__global__ void prep_kernel(const float* __restrict__ xyz)
{
    int i = blockIdx.x * 256 + threadIdx.x;   // over B*N
    float x = xyz[3 * i], y = xyz[3 * i + 1], z = xyz[3 * i + 2];
    float s = x * x + y * y + z * z;
    g_xyz4[i] = make_float4(x, y, z, s);
    float r = sqrtf(s);
    int loc = i & (N - 1);
    g_key[i] = ((unsigned long long)__float_as_uint(r) << 32) | (unsigned)loc;
}

// ---------------------------------------------------------------------------
// Kernel 0b: per-batch bitonic sort of 4096 (r, idx) keys, then materialize
// radius-sorted point array + orig-index map. One 1024-thread block per batch.
// ---------------------------------------------------------------------------
__global__ __launch_bounds__(1024) void sort_kernel()
{
    __shared__ unsigned long long sk[N];   // 32KB
    const int b = blockIdx.x;
    const int tid = threadIdx.x;

    for (int i = tid; i < N; i += 1024) sk[i] = g_key[b * N + i];
    __syncthreads();

    for (int k = 2; k <= N; k <<= 1) {
        for (int j = k >> 1; j > 0; j >>= 1) {
            for (int i = tid; i < N; i += 1024) {
                int l = i ^ j;
                if (l > i) {
                    bool up = ((i & k) == 0);
                    unsigned long long a = sk[i], c = sk[l];
                    if ((a > c) == up) { sk[i] = c; sk[l] = a; }
                }
            }
            __syncthreads();
        }
    }

    for (int i = tid; i < N; i += 1024) {
        unsigned long long key = sk[i];
        int idx = (int)(key & 0xFFFFFFFFu);
        g_srt[b * N + i]   = g_xyz4[b * N + idx];
        g_sorig[b * N + i] = idx;
    }
}

// ---------------------------------------------------------------------------
// Kernel 1: zbn[b][n][c] = relu(scale_c * (sum_k W[c][k] * x[b][k][n]) + bias_c)
// ---------------------------------------------------------------------------
__global__ __launch_bounds__(256) void gemm_bn_relu_kernel(
    const float* __restrict__ x,      // [B][C][N]
    const float* __restrict__ W,      // [C_out][C_in]
    const float* __restrict__ gamma,
    const float* __restrict__ beta,
    const float* __restrict__ rmean,
    const float* __restrict__ rvar)
{
    __shared__ float xs[32][64];
    __shared__ float ws[32][128];

    const int b  = blockIdx.y;
    const int n0 = blockIdx.x * 64;
    const int tid = threadIdx.x;
    const int tc = tid & 31;
    const int tn = tid >> 5;

    float acc[4][8];
#pragma unroll
    for (int j = 0; j < 4; ++j)
#pragma unroll
        for (int i = 0; i < 8; ++i) acc[j][i] = 0.0f;

    const float* xb = x + (size_t)b * C * N;

    for (int k0 = 0; k0 < C; k0 += 32) {
#pragma unroll
        for (int i = tid; i < 32 * 64; i += 256) {
            int kk = i >> 6, nn = i & 63;
            xs[kk][nn] = xb[(size_t)(k0 + kk) * N + n0 + nn];
        }
#pragma unroll
        for (int i = tid; i < 32 * 128; i += 256) {
            int c = i >> 5, kk = i & 31;
            ws[kk][c ^ ((kk & 7) << 2)] = W[c * C + k0 + kk];
        }
        __syncthreads();

#pragma unroll
        for (int kk = 0; kk < 32; ++kk) {
            float4 wv  = *(const float4*)&ws[kk][((tc ^ (kk & 7)) << 2)];
            float4 xv0 = *(const float4*)&xs[kk][tn * 8];
            float4 xv1 = *(const float4*)&xs[kk][tn * 8 + 4];
            float wj[4] = {wv.x, wv.y, wv.z, wv.w};
            float xi[8] = {xv0.x, xv0.y, xv0.z, xv0.w, xv1.x, xv1.y, xv1.z, xv1.w};
#pragma unroll
            for (int j = 0; j < 4; ++j)
#pragma unroll
                for (int i = 0; i < 8; ++i)
                    acc[j][i] = fmaf(wj[j], xi[i], acc[j][i]);
        }
        __syncthreads();
    }

    const int c0 = tc * 4;
    float sc[4], bi[4];
#pragma unroll
    for (int j = 0; j < 4; ++j) {
        sc[j] = gamma[c0 + j] * rsqrtf(rvar[c0 + j] + 1e-5f);
        bi[j] = beta[c0 + j] - rmean[c0 + j] * sc[j];
    }
#pragma unroll
    for (int i = 0; i < 8; ++i) {
        int n = n0 + tn * 8 + i;
        float4 o;
        o.x = fmaxf(fmaf(acc[0][i], sc[0], bi[0]), 0.0f);
        o.y = fmaxf(fmaf(acc[1][i], sc[1], bi[1]), 0.0f);
        o.z = fmaxf(fmaf(acc[2][i], sc[2], bi[2]), 0.0f);
        o.w = fmaxf(fmaf(acc[3][i], sc[3], bi[3]), 0.0f);
        *(float4*)&g_zbn[((size_t)b * N + n) * C + c0] = o;
    }
}

// ---------------------------------------------------------------------------
// Kernel 2: exact top-16 via radius-sorted window scan.
// Thread = (query-rank, direction-split). Split 0 scans ranks upward from the
// warp's seed window, split 1 scans downward. Both seed the warp's own 32
// ranks (identical lists) for an immediate tight threshold; merge dedups.
// Stop scanning a direction when (radius gap) > sqrt(thr) for all lanes:
// any unscanned point then has d >= (dr)^2 > thr  ->  exact.
// Block 128 = 64 queries x 2 splits. Grid (N/64, B) = 512 blocks.
// ---------------------------------------------------------------------------
__device__ __forceinline__ void insert16(float (&tv)[16], int (&ti)[16],
                                         float e, int jj)
{
#pragma unroll
    for (int t = 15; t >= 0; --t) {
        bool gt  = tv[t] > e;                   // strict: ties keep incumbent
        bool gtp = (t > 0) && (tv[t - 1] > e);
        float nv = gtp ? tv[t - 1] : e;
        int   ni = gtp ? ti[t - 1] : jj;
        if (gt) { tv[t] = nv; ti[t] = ni; }
    }
}

__global__ __launch_bounds__(128) void knn_kernel()
{
    __shared__ unsigned long long buf[16][128];  // accept buffer (16KB)
    __shared__ float mD[64][17];                 // merge staging
    __shared__ int   mI[64][17];

    const int tid  = threadIdx.x;
    const int lane = tid & 31;
    const int u    = tid & 63;                   // query slot in block
    const int s    = tid >> 6;                   // 0 = up-scan, 1 = down-scan
    const int b    = blockIdx.y;
    const int m    = blockIdx.x * 64 + u;        // my query's radius rank

    const float4* __restrict__ xb = g_srt   + (size_t)b * N;
    const int*    __restrict__ so = g_sorig + (size_t)b * N;

    const float4 Q  = __ldg(&xb[m]);
    const float  qs = Q.w;
    const float  rm = sqrtf(qs);
    const int sbase = m - lane;                  // warp's seed window base

    float tv[16]; int ti[16];
#pragma unroll
    for (int t = 0; t < 16; ++t) { tv[t] = CUDART_INF_F; ti[t] = 0; }

    // ---- seed: the warp's own 32 ranks (both splits: identical lists) ----
#pragma unroll 1
    for (int jj = sbase; jj < sbase + 32; ++jj) {
        float4 p = __ldg(&xb[jj]);
        float dot = Q.x * p.x;
        dot = fmaf(Q.y, p.y, dot);
        dot = fmaf(Q.z, p.z, dot);
        float d = fmaf(-2.0f, dot, qs + p.w);
        insert16(tv, ti, d, __ldg(&so[jj]));
    }
    float thr  = tv[15];
    float sthr = sqrtf(thr);

    unsigned addr0 = (unsigned)__cvta_generic_to_shared(&buf[0][0]) + tid * 8u;
    unsigned addr  = addr0;
    const unsigned athr = addr0 + 8u * 1024u;    // flush trigger: cnt >= 8

#define KNN_FLUSH() do {                                                      \
        int cnt = (int)((addr - addr0) >> 10);                                \
        int mx  = __reduce_max_sync(FULL, cnt);                               \
        for (int t = 0; t < mx; ++t) {                                        \
            unsigned long long e = buf[t][tid];                               \
            float ed = (t < cnt) ? __uint_as_float((unsigned)(e >> 32))       \
                                 : CUDART_INF_F;                              \
            int rk = ((int)(unsigned)e) & (N - 1);                            \
            int ej = __ldg(&so[rk]);                                          \
            insert16(tv, ti, ed, ej);                                         \
        }                                                                     \
        addr = addr0; thr = tv[15]; sthr = sqrtf(thr);                        \
    } while (0)

    if (s == 0) {
        // ---- up-scan: ranks sbase+32 .. 4095 ----
        int j = sbase + 32;
        while (true) {
            float edgew = CUDART_INF_F;
            if (j < N) {
#pragma unroll
                for (int uu = 0; uu < 8; ++uu) {
                    int jj = j + uu;
                    float4 p = (jj < N) ? __ldg(&xb[jj])
                                        : make_float4(0.f, 0.f, 0.f, CUDART_INF_F);
                    float dot = Q.x * p.x;
                    dot = fmaf(Q.y, p.y, dot);
                    dot = fmaf(Q.z, p.z, dot);
                    float d = fmaf(-2.0f, dot, qs + p.w);
                    unsigned long long pk =
                        ((unsigned long long)__float_as_uint(d) << 32) | (unsigned)jj;
                    asm volatile(
                        "{\n\t"
                        ".reg .pred p;\n\t"
                        "setp.lt.f32 p, %1, %2;\n\t"
                        "@p st.shared.b64 [%0], %3;\n\t"
                        "@p add.u32 %0, %0, 1024;\n\t"
                        "}"
                        : "+r"(addr) : "f"(d), "f"(thr), "l"(pk) : "memory");
                    if (uu == 7) edgew = p.w;
                }
                j += 8;
            }
            if (__any_sync(FULL, addr >= athr)) KNN_FLUSH();
            float redge = sqrtf(edgew);                    // inf if past end
            bool done = (j >= N) || ((redge - rm) > sthr);
            if (__all_sync(FULL, done)) break;
        }
    } else {
        // ---- down-scan: ranks sbase-1 .. 0 ----
        int j = sbase - 1;
        while (true) {
            float edgew = CUDART_INF_F;
            if (j >= 0) {
#pragma unroll
                for (int uu = 0; uu < 8; ++uu) {
                    int jj = j - uu;
                    float4 p = (jj >= 0) ? __ldg(&xb[jj])
                                         : make_float4(0.f, 0.f, 0.f, CUDART_INF_F);
                    float dot = Q.x * p.x;
                    dot = fmaf(Q.y, p.y, dot);
                    dot = fmaf(Q.z, p.z, dot);
                    float d = fmaf(-2.0f, dot, qs + p.w);
                    unsigned long long pk =
                        ((unsigned long long)__float_as_uint(d) << 32) | (unsigned)jj;
                    asm volatile(
                        "{\n\t"
                        ".reg .pred p;\n\t"
                        "setp.lt.f32 p, %1, %2;\n\t"
                        "@p st.shared.b64 [%0], %3;\n\t"
                        "@p add.u32 %0, %0, 1024;\n\t"
                        "}"
                        : "+r"(addr) : "f"(d), "f"(thr), "l"(pk) : "memory");
                    if (uu == 7) edgew = p.w;   // lowest rank in group
                }
                j -= 8;
            }
            if (__any_sync(FULL, addr >= athr)) KNN_FLUSH();
            float redge = sqrtf(edgew);
            bool done = (j < 0) || ((j < 0 ? true : false) || ((rm - redge) > sthr));
            done = (j < 0) || ((rm - redge) > sthr);
            if (__all_sync(FULL, done)) break;
        }
    }
    // final flush of pending accepts
    KNN_FLUSH();
#undef KNN_FLUSH

    // ---- merge: split 1 publishes, split 0 merges with seed-dedup ----
    if (s == 1) {
#pragma unroll
        for (int t = 0; t < 16; ++t) { mD[u][t] = tv[t]; mI[u][t] = ti[t]; }
    }
    __syncthreads();
    if (s == 0) {
#pragma unroll 1
        for (int t = 0; t < 16; ++t) {
            float ed = mD[u][t];
            int   ej = mI[u][t];
            bool dup = false;
#pragma unroll
            for (int r = 0; r < 16; ++r) dup |= (ti[r] == ej);
            if (!dup) insert16(tv, ti, ed, ej);
        }
        int orig = __ldg(&so[m]);
        int* op = g_idx + ((size_t)b * N + orig) * KNN;
#pragma unroll
        for (int t = 0; t < 16; ++t) op[t] = ti[t];
    }
}

// ---------------------------------------------------------------------------
// Kernel 3: gather-max over 16 neighbors + transpose to [B][C][N].
// ---------------------------------------------------------------------------
__global__ __launch_bounds__(256) void gather_kernel(float* __restrict__ out)
{
    __shared__ float sout[128][33];

    const int b    = blockIdx.y;
    const int n0   = blockIdx.x * 32;
    const int tid  = threadIdx.x;
    const int w    = tid >> 5;
    const int lane = tid & 31;

    const float* __restrict__ zb = g_zbn + (size_t)b * N * C;

    for (int s = 0; s < 4; ++s) {
        const int ql = w * 4 + s;
        const int n  = n0 + ql;
        int myidx = (lane < 16) ? g_idx[((size_t)b * N + n) * KNN + lane] : 0;

        float m0 = 0.0f, m1 = 0.0f, m2 = 0.0f, m3 = 0.0f;  // post-ReLU >= 0
#pragma unroll
        for (int t = 0; t < KNN; t += 2) {
            int j1 = __shfl_sync(FULL, myidx, t);
            int j2 = __shfl_sync(FULL, myidx, t + 1);
            const float* c1 = zb + ((size_t)j1 << 7);
            const float* c2 = zb + ((size_t)j2 << 7);
            float a0 = c1[lane], a1 = c1[lane + 32], a2 = c1[lane + 64], a3 = c1[lane + 96];
            float b0 = c2[lane], b1 = c2[lane + 32], b2 = c2[lane + 64], b3 = c2[lane + 96];
            m0 = fmaxf(m0, fmaxf(a0, b0));
            m1 = fmaxf(m1, fmaxf(a1, b1));
            m2 = fmaxf(m2, fmaxf(a2, b2));
            m3 = fmaxf(m3, fmaxf(a3, b3));
        }

        sout[lane][ql]      = m0;
        sout[lane + 32][ql] = m1;
        sout[lane + 64][ql] = m2;
        sout[lane + 96][ql] = m3;
    }
    __syncthreads();

    float* ob = out + (size_t)b * C * N + n0;
    for (int i = tid; i < 128 * 32; i += 256) {
        int c = i >> 5, nn = i & 31;
        ob[(size_t)c * N + nn] = sout[c][nn];
    }
}

// ---------------------------------------------------------------------------
extern "C" void kernel_launch(void* const* d_in, const int* in_sizes, int n_in,
                              void* d_out, int out_size)
{
    const float* xyz   = (const float*)d_in[0];
    const float* x     = (const float*)d_in[1];
    const float* W     = (const float*)d_in[2];
    const float* gamma = (const float*)d_in[3];
    const float* beta  = (const float*)d_in[4];
    const float* rmean = (const float*)d_in[5];
    const float* rvar  = (const float*)d_in[6];
    float* out = (float*)d_out;

    prep_kernel<<<B * N / 256, 256>>>(xyz);
    sort_kernel<<<B, 1024>>>();
    gemm_bn_relu_kernel<<<dim3(N / 64, B), 256>>>(x, W, gamma, beta, rmean, rvar);
    knn_kernel<<<dim3(N / 64, B), 128>>>();
    gather_kernel<<<dim3(N / 32, B), 256>>>(out);
}

// round 6
// speedup vs baseline: 1.4783x; 1.4783x over previous
#include <cuda_runtime.h>
#include <cuda_bf16.h>
#include <math_constants.h>

#define FULL 0xffffffffu

static constexpr int B = 8;
static constexpr int N = 4096;
static constexpr int C = 128;
static constexpr int KNN = 16;

// scratch (device globals: no allocation allowed)
__device__ float  g_zbn[B * N * C];    // zbn[b][n][c], n-major rows of 512B
__device__ float4 g_xyz4[B * N];       // (x,y,z,|p|^2)
__device__ int    g_idx[B * N * KNN];  // 16 NN indices per query

// ---------------------------------------------------------------------------
// Kernel 0: pack xyz + squared norm into float4
// ---------------------------------------------------------------------------
__global__ void prep_kernel(const float* __restrict__ xyz)
{
    int i = blockIdx.x * 256 + threadIdx.x;   // over B*N
    float x = xyz[3 * i], y = xyz[3 * i + 1], z = xyz[3 * i + 2];
    g_xyz4[i] = make_float4(x, y, z, x * x + y * y + z * z);
}

// ---------------------------------------------------------------------------
// Kernel 1: zbn[b][n][c] = relu(scale_c * (sum_k W[c][k] * x[b][k][n]) + bias_c)
// ---------------------------------------------------------------------------
__global__ __launch_bounds__(256) void gemm_bn_relu_kernel(
    const float* __restrict__ x,      // [B][C][N]
    const float* __restrict__ W,      // [C_out][C_in]
    const float* __restrict__ gamma,
    const float* __restrict__ beta,
    const float* __restrict__ rmean,
    const float* __restrict__ rvar)
{
    __shared__ float xs[32][64];    // [k][n]
    __shared__ float ws[32][128];   // [k][c], XOR-swizzled in 4-float units

    const int b  = blockIdx.y;
    const int n0 = blockIdx.x * 64;
    const int tid = threadIdx.x;
    const int tc = tid & 31;
    const int tn = tid >> 5;

    float acc[4][8];
#pragma unroll
    for (int j = 0; j < 4; ++j)
#pragma unroll
        for (int i = 0; i < 8; ++i) acc[j][i] = 0.0f;

    const float* xb = x + (size_t)b * C * N;

    for (int k0 = 0; k0 < C; k0 += 32) {
#pragma unroll
        for (int i = tid; i < 32 * 64; i += 256) {
            int kk = i >> 6, nn = i & 63;
            xs[kk][nn] = xb[(size_t)(k0 + kk) * N + n0 + nn];
        }
#pragma unroll
        for (int i = tid; i < 32 * 128; i += 256) {
            int c = i >> 5, kk = i & 31;
            ws[kk][c ^ ((kk & 7) << 2)] = W[c * C + k0 + kk];
        }
        __syncthreads();

#pragma unroll
        for (int kk = 0; kk < 32; ++kk) {
            float4 wv  = *(const float4*)&ws[kk][((tc ^ (kk & 7)) << 2)];
            float4 xv0 = *(const float4*)&xs[kk][tn * 8];
            float4 xv1 = *(const float4*)&xs[kk][tn * 8 + 4];
            float wj[4] = {wv.x, wv.y, wv.z, wv.w};
            float xi[8] = {xv0.x, xv0.y, xv0.z, xv0.w, xv1.x, xv1.y, xv1.z, xv1.w};
#pragma unroll
            for (int j = 0; j < 4; ++j)
#pragma unroll
                for (int i = 0; i < 8; ++i)
                    acc[j][i] = fmaf(wj[j], xi[i], acc[j][i]);
        }
        __syncthreads();
    }

    const int c0 = tc * 4;
    float sc[4], bi[4];
#pragma unroll
    for (int j = 0; j < 4; ++j) {
        sc[j] = gamma[c0 + j] * rsqrtf(rvar[c0 + j] + 1e-5f);
        bi[j] = beta[c0 + j] - rmean[c0 + j] * sc[j];
    }
#pragma unroll
    for (int i = 0; i < 8; ++i) {
        int n = n0 + tn * 8 + i;
        float4 o;
        o.x = fmaxf(fmaf(acc[0][i], sc[0], bi[0]), 0.0f);
        o.y = fmaxf(fmaf(acc[1][i], sc[1], bi[1]), 0.0f);
        o.z = fmaxf(fmaf(acc[2][i], sc[2], bi[2]), 0.0f);
        o.w = fmaxf(fmaf(acc[3][i], sc[3], bi[3]), 0.0f);
        *(float4*)&g_zbn[((size_t)b * N + n) * C + c0] = o;
    }
}

// ---------------------------------------------------------------------------
// Kernel 2: top-16 KNN, thread-per-(query,split), 4 splits of 1024 candidates.
// Branch-free accept path: setp + predicated STS.64 + predicated add (asm).
// 128-thread block = 32 queries x 4 splits (warp s owns split s for all 32
// queries). Splits 1-3 publish their sorted 16-lists through smem; warp 0
// merges in split order so index-order tie preference is preserved.
// Grid: (N/32, B) = 1024 blocks.
// ---------------------------------------------------------------------------
__device__ __forceinline__ void insert16(float (&tv)[16], int (&ti)[16],
                                         float e, int jj)
{
#pragma unroll
    for (int t = 15; t >= 0; --t) {
        bool gt  = tv[t] > e;                   // strict: ties keep incumbent
        bool gtp = (t > 0) && (tv[t - 1] > e);
        float nv = gtp ? tv[t - 1] : e;
        int   ni = gtp ? ti[t - 1] : jj;
        if (gt) { tv[t] = nv; ti[t] = ni; }
    }
}

__global__ __launch_bounds__(128) void knn_kernel()
{
    __shared__ unsigned long long buf[16][128];  // accept buffer, 16KB
    __shared__ float mD[32][3][17];              // merge staging (51-float row: conflict-free)
    __shared__ int   mI[32][3][17];

    const int tid  = threadIdx.x;
    const int lane = tid & 31;                   // query slot in block
    const int s    = tid >> 5;                   // split 0..3 (warp-homogeneous)
    const int b    = blockIdx.y;
    const int q    = blockIdx.x * 32 + lane;

    const float4* __restrict__ xb = g_xyz4 + (size_t)b * N;
    const float4 Q = __ldg(&xb[q]);
    const float qs = Q.w;

    float tv[16]; int ti[16];
#pragma unroll
    for (int t = 0; t < 16; ++t) { tv[t] = CUDART_INF_F; ti[t] = 0; }

    const int lo = s << 10;                      // s * 1024

    // ---- seed: first 32 candidates of own range, co-executed inserts ----
#pragma unroll 1
    for (int jj = 0; jj < 32; ++jj) {
        int j = lo + jj;
        float4 p = __ldg(&xb[j]);
        float dot = Q.x * p.x;
        dot = fmaf(Q.y, p.y, dot);
        dot = fmaf(Q.z, p.z, dot);
        float d = fmaf(-2.0f, dot, qs + p.w);
        insert16(tv, ti, d, j);
    }
    float thr = tv[15];

    unsigned addr0 = (unsigned)__cvta_generic_to_shared(&buf[0][0]) + tid * 8u;
    unsigned addr  = addr0;
    const unsigned athr = addr0 + 8u * 1024u;    // slot stride = 128*8 bytes

    // ---- main scan over own 1024-candidate range ----
#pragma unroll 1
    for (int j0 = lo + 32; j0 < lo + 1024; j0 += 8) {
#pragma unroll
        for (int uu = 0; uu < 8; ++uu) {
            int j = j0 + uu;
            float4 p = __ldg(&xb[j]);
            float dot = Q.x * p.x;
            dot = fmaf(Q.y, p.y, dot);
            dot = fmaf(Q.z, p.z, dot);
            float d = fmaf(-2.0f, dot, qs + p.w);
            unsigned long long pk =
                ((unsigned long long)__float_as_uint(d) << 32) | (unsigned)j;
            asm volatile(
                "{\n\t"
                ".reg .pred p;\n\t"
                "setp.lt.f32 p, %1, %2;\n\t"
                "@p st.shared.b64 [%0], %3;\n\t"
                "@p add.u32 %0, %0, 1024;\n\t"
                "}"
                : "+r"(addr) : "f"(d), "f"(thr), "l"(pk) : "memory");
        }
        if (__any_sync(FULL, addr >= athr)) {    // uniform predicate -> plain BRA
            int cnt = (int)((addr - addr0) >> 10);
            int mx  = __reduce_max_sync(FULL, cnt);
#pragma unroll 1
            for (int t = 0; t < mx; ++t) {
                unsigned long long e = buf[t][tid];
                float ed = (t < cnt) ? __uint_as_float((unsigned)(e >> 32))
                                     : CUDART_INF_F;
                int   ej = (int)(unsigned)e;
                insert16(tv, ti, ed, ej);
            }
            addr = addr0;
            thr  = tv[15];
        }
    }
    // ---- final flush ----
    if (__any_sync(FULL, addr != addr0)) {
        int cnt = (int)((addr - addr0) >> 10);
        int mx  = __reduce_max_sync(FULL, cnt);
#pragma unroll 1
        for (int t = 0; t < mx; ++t) {
            unsigned long long e = buf[t][tid];
            float ed = (t < cnt) ? __uint_as_float((unsigned)(e >> 32))
                                 : CUDART_INF_F;
            int   ej = (int)(unsigned)e;
            insert16(tv, ti, ed, ej);
        }
    }

    // ---- merge splits 1..3 into split 0 (ascending split = ascending index
    //      range, so strict-incumbent insert keeps the lower index on ties) ----
    if (s != 0) {
#pragma unroll
        for (int t = 0; t < 16; ++t) {
            mD[lane][s - 1][t] = tv[t];
            mI[lane][s - 1][t] = ti[t];
        }
    }
    __syncthreads();
    if (s == 0) {
#pragma unroll 1
        for (int k = 0; k < 3; ++k)
#pragma unroll 1
            for (int t = 0; t < 16; ++t)
                insert16(tv, ti, mD[lane][k][t], mI[lane][k][t]);

        int* op = g_idx + ((size_t)b * N + q) * KNN;
#pragma unroll
        for (int t = 0; t < 16; ++t) op[t] = ti[t];
    }
}

// ---------------------------------------------------------------------------
// Kernel 3: gather-max over 16 neighbors + transpose to [B][C][N].
// Warp per query (4 queries/warp), 256 threads. Grid: (N/32, B).
// ---------------------------------------------------------------------------
__global__ __launch_bounds__(256) void gather_kernel(float* __restrict__ out)
{
    __shared__ float sout[128][33];

    const int b    = blockIdx.y;
    const int n0   = blockIdx.x * 32;
    const int tid  = threadIdx.x;
    const int w    = tid >> 5;
    const int lane = tid & 31;

    const float* __restrict__ zb = g_zbn + (size_t)b * N * C;

    for (int s = 0; s < 4; ++s) {
        const int ql = w * 4 + s;
        const int n  = n0 + ql;
        int myidx = (lane < 16) ? g_idx[((size_t)b * N + n) * KNN + lane] : 0;

        float m0 = 0.0f, m1 = 0.0f, m2 = 0.0f, m3 = 0.0f;  // post-ReLU >= 0
#pragma unroll
        for (int t = 0; t < KNN; t += 2) {
            int j1 = __shfl_sync(FULL, myidx, t);
            int j2 = __shfl_sync(FULL, myidx, t + 1);
            const float* c1 = zb + ((size_t)j1 << 7);
            const float* c2 = zb + ((size_t)j2 << 7);
            float a0 = c1[lane], a1 = c1[lane + 32], a2 = c1[lane + 64], a3 = c1[lane + 96];
            float b0 = c2[lane], b1 = c2[lane + 32], b2 = c2[lane + 64], b3 = c2[lane + 96];
            m0 = fmaxf(m0, fmaxf(a0, b0));
            m1 = fmaxf(m1, fmaxf(a1, b1));
            m2 = fmaxf(m2, fmaxf(a2, b2));
            m3 = fmaxf(m3, fmaxf(a3, b3));
        }

        sout[lane][ql]      = m0;
        sout[lane + 32][ql] = m1;
        sout[lane + 64][ql] = m2;
        sout[lane + 96][ql] = m3;
    }
    __syncthreads();

    float* ob = out + (size_t)b * C * N + n0;
    for (int i = tid; i < 128 * 32; i += 256) {
        int c = i >> 5, nn = i & 31;
        ob[(size_t)c * N + nn] = sout[c][nn];
    }
}

// ---------------------------------------------------------------------------
extern "C" void kernel_launch(void* const* d_in, const int* in_sizes, int n_in,
                              void* d_out, int out_size)
{
    const float* xyz   = (const float*)d_in[0];
    const float* x     = (const float*)d_in[1];
    const float* W     = (const float*)d_in[2];
    const float* gamma = (const float*)d_in[3];
    const float* beta  = (const float*)d_in[4];
    const float* rmean = (const float*)d_in[5];
    const float* rvar  = (const float*)d_in[6];
    float* out = (float*)d_out;

    prep_kernel<<<B * N / 256, 256>>>(xyz);
    gemm_bn_relu_kernel<<<dim3(N / 64, B), 256>>>(x, W, gamma, beta, rmean, rvar);
    knn_kernel<<<dim3(N / 32, B), 128>>>();
    gather_kernel<<<dim3(N / 32, B), 256>>>(out);
}

// round 7
// speedup vs baseline: 1.5939x; 1.0782x over previous
#include <cuda_runtime.h>
#include <cuda_bf16.h>
#include <cuda_fp16.h>
#include <math_constants.h>

#define FULL 0xffffffffu

static constexpr int B = 8;
static constexpr int N = 4096;
static constexpr int C = 128;
static constexpr int KNN = 16;

// scratch (device globals: no allocation allowed)
__device__ __half g_zbn[B * N * C];    // zbn[b][n][c] fp16, n-major rows 256B
__device__ float4 g_xyz4[B * N];       // (x,y,z,|p|^2)
__device__ int    g_idx[B * N * KNN];  // 16 NN indices per query

// ---------------------------------------------------------------------------
// Kernel 0: pack xyz + squared norm into float4
// ---------------------------------------------------------------------------
__global__ void prep_kernel(const float* __restrict__ xyz)
{
    int i = blockIdx.x * 256 + threadIdx.x;   // over B*N
    float x = xyz[3 * i], y = xyz[3 * i + 1], z = xyz[3 * i + 2];
    g_xyz4[i] = make_float4(x, y, z, x * x + y * y + z * z);
}

// ---------------------------------------------------------------------------
// Kernel 1: zbn[b][n][c] = relu(scale_c * (sum_k W[c][k] * x[b][k][n]) + bias_c)
// fp32 math, fp16 store.
// ---------------------------------------------------------------------------
__global__ __launch_bounds__(256) void gemm_bn_relu_kernel(
    const float* __restrict__ x,      // [B][C][N]
    const float* __restrict__ W,      // [C_out][C_in]
    const float* __restrict__ gamma,
    const float* __restrict__ beta,
    const float* __restrict__ rmean,
    const float* __restrict__ rvar)
{
    __shared__ float xs[32][64];    // [k][n]
    __shared__ float ws[32][128];   // [k][c], XOR-swizzled in 4-float units

    const int b  = blockIdx.y;
    const int n0 = blockIdx.x * 64;
    const int tid = threadIdx.x;
    const int tc = tid & 31;
    const int tn = tid >> 5;

    float acc[4][8];
#pragma unroll
    for (int j = 0; j < 4; ++j)
#pragma unroll
        for (int i = 0; i < 8; ++i) acc[j][i] = 0.0f;

    const float* xb = x + (size_t)b * C * N;

    for (int k0 = 0; k0 < C; k0 += 32) {
#pragma unroll
        for (int i = tid; i < 32 * 64; i += 256) {
            int kk = i >> 6, nn = i & 63;
            xs[kk][nn] = xb[(size_t)(k0 + kk) * N + n0 + nn];
        }
#pragma unroll
        for (int i = tid; i < 32 * 128; i += 256) {
            int c = i >> 5, kk = i & 31;
            ws[kk][c ^ ((kk & 7) << 2)] = W[c * C + k0 + kk];
        }
        __syncthreads();

#pragma unroll
        for (int kk = 0; kk < 32; ++kk) {
            float4 wv  = *(const float4*)&ws[kk][((tc ^ (kk & 7)) << 2)];
            float4 xv0 = *(const float4*)&xs[kk][tn * 8];
            float4 xv1 = *(const float4*)&xs[kk][tn * 8 + 4];
            float wj[4] = {wv.x, wv.y, wv.z, wv.w};
            float xi[8] = {xv0.x, xv0.y, xv0.z, xv0.w, xv1.x, xv1.y, xv1.z, xv1.w};
#pragma unroll
            for (int j = 0; j < 4; ++j)
#pragma unroll
                for (int i = 0; i < 8; ++i)
                    acc[j][i] = fmaf(wj[j], xi[i], acc[j][i]);
        }
        __syncthreads();
    }

    const int c0 = tc * 4;
    float sc[4], bi[4];
#pragma unroll
    for (int j = 0; j < 4; ++j) {
        sc[j] = gamma[c0 + j] * rsqrtf(rvar[c0 + j] + 1e-5f);
        bi[j] = beta[c0 + j] - rmean[c0 + j] * sc[j];
    }
#pragma unroll
    for (int i = 0; i < 8; ++i) {
        int n = n0 + tn * 8 + i;
        float ox = fmaxf(fmaf(acc[0][i], sc[0], bi[0]), 0.0f);
        float oy = fmaxf(fmaf(acc[1][i], sc[1], bi[1]), 0.0f);
        float oz = fmaxf(fmaf(acc[2][i], sc[2], bi[2]), 0.0f);
        float ow = fmaxf(fmaf(acc[3][i], sc[3], bi[3]), 0.0f);
        __half2 h01 = __floats2half2_rn(ox, oy);
        __half2 h23 = __floats2half2_rn(oz, ow);
        uint2 u;
        u.x = *reinterpret_cast<unsigned*>(&h01);
        u.y = *reinterpret_cast<unsigned*>(&h23);
        *(uint2*)&g_zbn[((size_t)b * N + n) * C + c0] = u;
    }
}

// ---------------------------------------------------------------------------
// Kernel 2: top-16 KNN, thread-per-(query,split), 4 splits of 1024 candidates.
// Shared cross-split threshold (monotone decreasing; stale reads only loosen
// the filter -> still exact). Branch-free accept: setp + predicated
// st.shared.v2.b32 + predicated add. 128-thr block = 32 queries x 4 splits.
// Grid: (N/32, B) = 1024 blocks.
// ---------------------------------------------------------------------------
__device__ __forceinline__ void insert16(float (&tv)[16], int (&ti)[16],
                                         float e, int jj)
{
#pragma unroll
    for (int t = 15; t >= 0; --t) {
        bool gt  = tv[t] > e;                   // strict: ties keep incumbent
        bool gtp = (t > 0) && (tv[t - 1] > e);
        float nv = gtp ? tv[t - 1] : e;
        int   ni = gtp ? ti[t - 1] : jj;
        if (gt) { tv[t] = nv; ti[t] = ni; }
    }
}

__global__ __launch_bounds__(128) void knn_kernel()
{
    __shared__ unsigned long long buf[16][128];  // accept buffer, 16KB
    __shared__ float sthr[32][5];                // per-query split thresholds (padded)
    __shared__ float mD[32][3][17];              // merge staging
    __shared__ int   mI[32][3][17];

    const int tid  = threadIdx.x;
    const int lane = tid & 31;                   // query slot in block
    const int s    = tid >> 5;                   // split 0..3 (warp-homogeneous)
    const int b    = blockIdx.y;
    const int q    = blockIdx.x * 32 + lane;

    // init shared thresholds
    for (int i = tid; i < 32 * 5; i += 128) ((float*)sthr)[i] = CUDART_INF_F;
    __syncthreads();

    const float4* __restrict__ xb = g_xyz4 + (size_t)b * N;
    const float4 Q = __ldg(&xb[q]);
    const float qs = Q.w;

    float tv[16]; int ti[16];
#pragma unroll
    for (int t = 0; t < 16; ++t) { tv[t] = CUDART_INF_F; ti[t] = 0; }

    const int lo = s << 10;                      // s * 1024

    // ---- seed: first 16 candidates of own range, co-executed inserts ----
#pragma unroll 1
    for (int jj = 0; jj < 16; ++jj) {
        int j = lo + jj;
        float4 p = __ldg(&xb[j]);
        float dot = Q.x * p.x;
        dot = fmaf(Q.y, p.y, dot);
        dot = fmaf(Q.z, p.z, dot);
        float d = fmaf(-2.0f, dot, qs + p.w);
        insert16(tv, ti, d, j);
    }
    sthr[lane][s] = tv[15];
    float fthr = fminf(fminf(sthr[lane][0], sthr[lane][1]),
                       fminf(sthr[lane][2], sthr[lane][3]));

    unsigned addr0 = (unsigned)__cvta_generic_to_shared(&buf[0][0]) + tid * 8u;
    unsigned addr  = addr0;
    const unsigned athr = addr0 + 8u * 1024u;    // slot stride = 128*8 bytes

#define KNN_FLUSH() do {                                                      \
        int cnt = (int)((addr - addr0) >> 10);                                \
        int mx  = __reduce_max_sync(FULL, cnt);                               \
        for (int t = 0; t < mx; ++t) {                                        \
            unsigned long long e = buf[t][tid];                               \
            float ed = (t < cnt) ? __uint_as_float((unsigned)(e >> 32))       \
                                 : CUDART_INF_F;                              \
            int   ej = (int)(unsigned)e;                                      \
            insert16(tv, ti, ed, ej);                                         \
        }                                                                     \
        addr = addr0;                                                         \
        sthr[lane][s] = tv[15];                                               \
        fthr = fminf(fminf(sthr[lane][0], sthr[lane][1]),                     \
                     fminf(sthr[lane][2], sthr[lane][3]));                    \
    } while (0)

    // ---- main scan over own 1024-candidate range ----
#pragma unroll 1
    for (int j0 = lo + 16; j0 < lo + 1024; j0 += 8) {
#pragma unroll
        for (int uu = 0; uu < 8; ++uu) {
            int j = j0 + uu;
            float4 p = __ldg(&xb[j]);
            float dot = Q.x * p.x;
            dot = fmaf(Q.y, p.y, dot);
            dot = fmaf(Q.z, p.z, dot);
            float d = fmaf(-2.0f, dot, qs + p.w);
            unsigned db = __float_as_uint(d);
            asm volatile(
                "{\n\t"
                ".reg .pred p;\n\t"
                "setp.lt.f32 p, %1, %2;\n\t"
                "@p st.shared.v2.b32 [%0], {%3, %4};\n\t"
                "@p add.u32 %0, %0, 1024;\n\t"
                "}"
                : "+r"(addr) : "f"(d), "f"(fthr), "r"(j), "r"(db) : "memory");
        }
        if (__any_sync(FULL, addr >= athr)) KNN_FLUSH();
    }
    // ---- final flush ----
    if (__any_sync(FULL, addr != addr0)) KNN_FLUSH();
#undef KNN_FLUSH

    // ---- merge splits 1..3 into split 0 (ascending split = ascending index
    //      range; strict-incumbent insert keeps lower index on ties) ----
    if (s != 0) {
#pragma unroll
        for (int t = 0; t < 16; ++t) {
            mD[lane][s - 1][t] = tv[t];
            mI[lane][s - 1][t] = ti[t];
        }
    }
    __syncthreads();
    if (s == 0) {
#pragma unroll 1
        for (int k = 0; k < 3; ++k)
#pragma unroll 1
            for (int t = 0; t < 16; ++t)
                insert16(tv, ti, mD[lane][k][t], mI[lane][k][t]);

        int* op = g_idx + ((size_t)b * N + q) * KNN;
#pragma unroll
        for (int t = 0; t < 16; ++t) op[t] = ti[t];
    }
}

// ---------------------------------------------------------------------------
// Kernel 3: gather-max over 16 neighbors (fp16 rows, one LDG.64 + 2 HMNMX2
// per row per lane) + transpose to [B][C][N] float.
// Warp per query (4 queries/warp), 256 threads. Grid: (N/32, B).
// ---------------------------------------------------------------------------
__global__ __launch_bounds__(256) void gather_kernel(float* __restrict__ out)
{
    __shared__ float sout[128][33];

    const int b    = blockIdx.y;
    const int n0   = blockIdx.x * 32;
    const int tid  = threadIdx.x;
    const int w    = tid >> 5;
    const int lane = tid & 31;

    const __half* __restrict__ zb = g_zbn + (size_t)b * N * C;

    for (int s = 0; s < 4; ++s) {
        const int ql = w * 4 + s;
        const int n  = n0 + ql;
        int myidx = (lane < 16) ? g_idx[((size_t)b * N + n) * KNN + lane] : 0;

        __half2 m01 = __float2half2_rn(0.0f);   // post-ReLU >= 0
        __half2 m23 = __float2half2_rn(0.0f);
#pragma unroll
        for (int t = 0; t < KNN; t += 2) {
            int j1 = __shfl_sync(FULL, myidx, t);
            int j2 = __shfl_sync(FULL, myidx, t + 1);
            const uint2* r1 = (const uint2*)(zb + ((size_t)j1 << 7));
            const uint2* r2 = (const uint2*)(zb + ((size_t)j2 << 7));
            uint2 u1 = __ldg(&r1[lane]);
            uint2 u2 = __ldg(&r2[lane]);
            m01 = __hmax2(m01, *reinterpret_cast<__half2*>(&u1.x));
            m23 = __hmax2(m23, *reinterpret_cast<__half2*>(&u1.y));
            m01 = __hmax2(m01, *reinterpret_cast<__half2*>(&u2.x));
            m23 = __hmax2(m23, *reinterpret_cast<__half2*>(&u2.y));
        }

        float2 f01 = __half22float2(m01);
        float2 f23 = __half22float2(m23);
        sout[4 * lane + 0][ql] = f01.x;
        sout[4 * lane + 1][ql] = f01.y;
        sout[4 * lane + 2][ql] = f23.x;
        sout[4 * lane + 3][ql] = f23.y;
    }
    __syncthreads();

    float* ob = out + (size_t)b * C * N + n0;
    for (int i = tid; i < 128 * 32; i += 256) {
        int c = i >> 5, nn = i & 31;
        ob[(size_t)c * N + nn] = sout[c][nn];
    }
}

// ---------------------------------------------------------------------------
extern "C" void kernel_launch(void* const* d_in, const int* in_sizes, int n_in,
                              void* d_out, int out_size)
{
    const float* xyz   = (const float*)d_in[0];
    const float* x     = (const float*)d_in[1];
    const float* W     = (const float*)d_in[2];
    const float* gamma = (const float*)d_in[3];
    const float* beta  = (const float*)d_in[4];
    const float* rmean = (const float*)d_in[5];
    const float* rvar  = (const float*)d_in[6];
    float* out = (float*)d_out;

    prep_kernel<<<B * N / 256, 256>>>(xyz);
    gemm_bn_relu_kernel<<<dim3(N / 64, B), 256>>>(x, W, gamma, beta, rmean, rvar);
    knn_kernel<<<dim3(N / 32, B), 128>>>();
    gather_kernel<<<dim3(N / 32, B), 256>>>(out);
}

// round 8
// speedup vs baseline: 1.6241x; 1.0189x over previous
#include <cuda_runtime.h>
#include <cuda_bf16.h>
#include <cuda_fp16.h>
#include <math_constants.h>

#define FULL 0xffffffffu

static constexpr int B = 8;
static constexpr int N = 4096;
static constexpr int C = 128;
static constexpr int KNN = 16;

// scratch (device globals: no allocation allowed)
__device__ __half g_zbn[B * N * C];    // zbn[b][n][c] fp16, n-major rows 256B
__device__ float4 g_xyz4[B * N];       // (x,y,z,|p|^2)
__device__ int    g_idx[B * N * KNN];  // 16 NN indices per query

// ---------------------------------------------------------------------------
// Kernel 0: pack xyz + squared norm into float4
// ---------------------------------------------------------------------------
__global__ void prep_kernel(const float* __restrict__ xyz)
{
    int i = blockIdx.x * 256 + threadIdx.x;   // over B*N
    float x = xyz[3 * i], y = xyz[3 * i + 1], z = xyz[3 * i + 2];
    g_xyz4[i] = make_float4(x, y, z, x * x + y * y + z * z);
}

// ---------------------------------------------------------------------------
// Kernel 1: zbn[b][n][c] = relu(scale_c * (sum_k W[c][k] * x[b][k][n]) + bias_c)
// fp32 math, fp16 store.
// ---------------------------------------------------------------------------
__global__ __launch_bounds__(256) void gemm_bn_relu_kernel(
    const float* __restrict__ x,      // [B][C][N]
    const float* __restrict__ W,      // [C_out][C_in]
    const float* __restrict__ gamma,
    const float* __restrict__ beta,
    const float* __restrict__ rmean,
    const float* __restrict__ rvar)
{
    __shared__ float xs[32][64];    // [k][n]
    __shared__ float ws[32][128];   // [k][c], XOR-swizzled in 4-float units

    const int b  = blockIdx.y;
    const int n0 = blockIdx.x * 64;
    const int tid = threadIdx.x;
    const int tc = tid & 31;
    const int tn = tid >> 5;

    float acc[4][8];
#pragma unroll
    for (int j = 0; j < 4; ++j)
#pragma unroll
        for (int i = 0; i < 8; ++i) acc[j][i] = 0.0f;

    const float* xb = x + (size_t)b * C * N;

    for (int k0 = 0; k0 < C; k0 += 32) {
#pragma unroll
        for (int i = tid; i < 32 * 64; i += 256) {
            int kk = i >> 6, nn = i & 63;
            xs[kk][nn] = xb[(size_t)(k0 + kk) * N + n0 + nn];
        }
#pragma unroll
        for (int i = tid; i < 32 * 128; i += 256) {
            int c = i >> 5, kk = i & 31;
            ws[kk][c ^ ((kk & 7) << 2)] = W[c * C + k0 + kk];
        }
        __syncthreads();

#pragma unroll
        for (int kk = 0; kk < 32; ++kk) {
            float4 wv  = *(const float4*)&ws[kk][((tc ^ (kk & 7)) << 2)];
            float4 xv0 = *(const float4*)&xs[kk][tn * 8];
            float4 xv1 = *(const float4*)&xs[kk][tn * 8 + 4];
            float wj[4] = {wv.x, wv.y, wv.z, wv.w};
            float xi[8] = {xv0.x, xv0.y, xv0.z, xv0.w, xv1.x, xv1.y, xv1.z, xv1.w};
#pragma unroll
            for (int j = 0; j < 4; ++j)
#pragma unroll
                for (int i = 0; i < 8; ++i)
                    acc[j][i] = fmaf(wj[j], xi[i], acc[j][i]);
        }
        __syncthreads();
    }

    const int c0 = tc * 4;
    float sc[4], bi[4];
#pragma unroll
    for (int j = 0; j < 4; ++j) {
        sc[j] = gamma[c0 + j] * rsqrtf(rvar[c0 + j] + 1e-5f);
        bi[j] = beta[c0 + j] - rmean[c0 + j] * sc[j];
    }
#pragma unroll
    for (int i = 0; i < 8; ++i) {
        int n = n0 + tn * 8 + i;
        float ox = fmaxf(fmaf(acc[0][i], sc[0], bi[0]), 0.0f);
        float oy = fmaxf(fmaf(acc[1][i], sc[1], bi[1]), 0.0f);
        float oz = fmaxf(fmaf(acc[2][i], sc[2], bi[2]), 0.0f);
        float ow = fmaxf(fmaf(acc[3][i], sc[3], bi[3]), 0.0f);
        __half2 h01 = __floats2half2_rn(ox, oy);
        __half2 h23 = __floats2half2_rn(oz, ow);
        uint2 u;
        u.x = *reinterpret_cast<unsigned*>(&h01);
        u.y = *reinterpret_cast<unsigned*>(&h23);
        *(uint2*)&g_zbn[((size_t)b * N + n) * C + c0] = u;
    }
}

// ---------------------------------------------------------------------------
// Kernel 2: top-16 KNN, thread-per-(query,split), 4 splits of 1024 candidates.
// Candidates staged through shared memory in lockstep tiles: iteration it
// stages chunk [s*1024 + it*256, +256) for every split s; warp s scans its
// own chunk via broadcast LDS (kills the L1-thrash of per-thread LDG streams).
// Scan order / flush / merge identical to round-7 (bit-identical results).
// Shared cross-split threshold; branch-free accept (setp + predicated STS).
// 128-thr block = 32 queries x 4 splits. Grid: (N/32, B) = 1024 blocks.
// ---------------------------------------------------------------------------
__device__ __forceinline__ void insert16(float (&tv)[16], int (&ti)[16],
                                         float e, int jj)
{
#pragma unroll
    for (int t = 15; t >= 0; --t) {
        bool gt  = tv[t] > e;                   // strict: ties keep incumbent
        bool gtp = (t > 0) && (tv[t - 1] > e);
        float nv = gtp ? tv[t - 1] : e;
        int   ni = gtp ? ti[t - 1] : jj;
        if (gt) { tv[t] = nv; ti[t] = ni; }
    }
}

__global__ __launch_bounds__(128) void knn_kernel()
{
    __shared__ unsigned long long buf[16][128];  // accept buffer, 16KB
    __shared__ float4 tile[1024];                // 4 chunks x 256 points, 16KB
    __shared__ float sthr[32][5];                // per-query split thresholds

    const int tid  = threadIdx.x;
    const int lane = tid & 31;                   // query slot in block
    const int s    = tid >> 5;                   // split 0..3 (warp-homogeneous)
    const int b    = blockIdx.y;
    const int q    = blockIdx.x * 32 + lane;

    // init shared thresholds
    for (int i = tid; i < 32 * 5; i += 128) ((float*)sthr)[i] = CUDART_INF_F;

    const float4* __restrict__ xb = g_xyz4 + (size_t)b * N;
    const float4 Q = __ldg(&xb[q]);
    const float qs = Q.w;

    float tv[16]; int ti[16];
#pragma unroll
    for (int t = 0; t < 16; ++t) { tv[t] = CUDART_INF_F; ti[t] = 0; }

    const int lo = s << 10;                      // s * 1024
    const float4* __restrict__ mychunk = tile + (s << 8);

    unsigned addr0 = (unsigned)__cvta_generic_to_shared(&buf[0][0]) + tid * 8u;
    unsigned addr  = addr0;
    const unsigned athr = addr0 + 8u * 1024u;    // slot stride = 128*8 bytes
    float fthr = CUDART_INF_F;

#define KNN_FLUSH() do {                                                      \
        int cnt = (int)((addr - addr0) >> 10);                                \
        int mx  = __reduce_max_sync(FULL, cnt);                               \
        for (int t = 0; t < mx; ++t) {                                        \
            unsigned long long e = buf[t][tid];                               \
            float ed = (t < cnt) ? __uint_as_float((unsigned)(e >> 32))       \
                                 : CUDART_INF_F;                              \
            int   ej = (int)(unsigned)e;                                      \
            insert16(tv, ti, ed, ej);                                         \
        }                                                                     \
        addr = addr0;                                                         \
        sthr[lane][s] = tv[15];                                               \
        fthr = fminf(fminf(sthr[lane][0], sthr[lane][1]),                     \
                     fminf(sthr[lane][2], sthr[lane][3]));                    \
    } while (0)

#pragma unroll 1
    for (int it = 0; it < 4; ++it) {
        // ---- stage 4x256 chunk tile (coalesced; protects prior-iter reads) ----
        __syncthreads();
#pragma unroll
        for (int k = 0; k < 8; ++k) {
            int flat = tid + (k << 7);           // 0..1023
            int ch = flat >> 8, off = flat & 255;
            tile[flat] = __ldg(&xb[(ch << 10) + (it << 8) + off]);
        }
        __syncthreads();

        const int jbase = lo + (it << 8);
        int t0 = 0;

        if (it == 0) {
            // ---- seed: first 16 candidates of own range, co-executed inserts ----
#pragma unroll 1
            for (int jj = 0; jj < 16; ++jj) {
                float4 p = mychunk[jj];
                float dot = Q.x * p.x;
                dot = fmaf(Q.y, p.y, dot);
                dot = fmaf(Q.z, p.z, dot);
                float d = fmaf(-2.0f, dot, qs + p.w);
                insert16(tv, ti, d, jbase + jj);
            }
            sthr[lane][s] = tv[15];
            fthr = fminf(fminf(sthr[lane][0], sthr[lane][1]),
                         fminf(sthr[lane][2], sthr[lane][3]));
            t0 = 16;
        }

        // ---- scan chunk via broadcast LDS ----
#pragma unroll 1
        for (; t0 < 256; t0 += 8) {
#pragma unroll
            for (int uu = 0; uu < 8; ++uu) {
                float4 p = mychunk[t0 + uu];
                float dot = Q.x * p.x;
                dot = fmaf(Q.y, p.y, dot);
                dot = fmaf(Q.z, p.z, dot);
                float d = fmaf(-2.0f, dot, qs + p.w);
                int j = jbase + t0 + uu;
                unsigned db = __float_as_uint(d);
                asm volatile(
                    "{\n\t"
                    ".reg .pred p;\n\t"
                    "setp.lt.f32 p, %1, %2;\n\t"
                    "@p st.shared.v2.b32 [%0], {%3, %4};\n\t"
                    "@p add.u32 %0, %0, 1024;\n\t"
                    "}"
                    : "+r"(addr) : "f"(d), "f"(fthr), "r"(j), "r"(db) : "memory");
            }
            if (__any_sync(FULL, addr >= athr)) KNN_FLUSH();
        }
    }
    // ---- final flush ----
    if (__any_sync(FULL, addr != addr0)) KNN_FLUSH();
#undef KNN_FLUSH

    // ---- merge splits 1..3 into split 0 (ascending split order preserves
    //      lower-index-on-tie). Staging overlays the dead accept buffer. ----
    __syncthreads();                             // all flush reads of buf done
    float (*mD)[3][17] = (float(*)[3][17])&buf[0][0];
    int   (*mI)[3][17] = (int(*)[3][17])((float*)&buf[0][0] + 32 * 3 * 17);

    if (s != 0) {
#pragma unroll
        for (int t = 0; t < 16; ++t) {
            mD[lane][s - 1][t] = tv[t];
            mI[lane][s - 1][t] = ti[t];
        }
    }
    __syncthreads();
    if (s == 0) {
#pragma unroll 1
        for (int k = 0; k < 3; ++k)
#pragma unroll 1
            for (int t = 0; t < 16; ++t)
                insert16(tv, ti, mD[lane][k][t], mI[lane][k][t]);

        int* op = g_idx + ((size_t)b * N + q) * KNN;
#pragma unroll
        for (int t = 0; t < 16; ++t) op[t] = ti[t];
    }
}

// ---------------------------------------------------------------------------
// Kernel 3: gather-max over 16 neighbors (fp16 rows, one LDG.64 + 2 HMNMX2
// per row per lane) + transpose to [B][C][N] float.
// Warp per query (4 queries/warp), 256 threads. Grid: (N/32, B).
// ---------------------------------------------------------------------------
__global__ __launch_bounds__(256) void gather_kernel(float* __restrict__ out)
{
    __shared__ float sout[128][33];

    const int b    = blockIdx.y;
    const int n0   = blockIdx.x * 32;
    const int tid  = threadIdx.x;
    const int w    = tid >> 5;
    const int lane = tid & 31;

    const __half* __restrict__ zb = g_zbn + (size_t)b * N * C;

    for (int s = 0; s < 4; ++s) {
        const int ql = w * 4 + s;
        const int n  = n0 + ql;
        int myidx = (lane < 16) ? g_idx[((size_t)b * N + n) * KNN + lane] : 0;

        __half2 m01 = __float2half2_rn(0.0f);   // post-ReLU >= 0
        __half2 m23 = __float2half2_rn(0.0f);
#pragma unroll
        for (int t = 0; t < KNN; t += 2) {
            int j1 = __shfl_sync(FULL, myidx, t);
            int j2 = __shfl_sync(FULL, myidx, t + 1);
            const uint2* r1 = (const uint2*)(zb + ((size_t)j1 << 7));
            const uint2* r2 = (const uint2*)(zb + ((size_t)j2 << 7));
            uint2 u1 = __ldg(&r1[lane]);
            uint2 u2 = __ldg(&r2[lane]);
            m01 = __hmax2(m01, *reinterpret_cast<__half2*>(&u1.x));
            m23 = __hmax2(m23, *reinterpret_cast<__half2*>(&u1.y));
            m01 = __hmax2(m01, *reinterpret_cast<__half2*>(&u2.x));
            m23 = __hmax2(m23, *reinterpret_cast<__half2*>(&u2.y));
        }

        float2 f01 = __half22float2(m01);
        float2 f23 = __half22float2(m23);
        sout[4 * lane + 0][ql] = f01.x;
        sout[4 * lane + 1][ql] = f01.y;
        sout[4 * lane + 2][ql] = f23.x;
        sout[4 * lane + 3][ql] = f23.y;
    }
    __syncthreads();

    float* ob = out + (size_t)b * C * N + n0;
    for (int i = tid; i < 128 * 32; i += 256) {
        int c = i >> 5, nn = i & 31;
        ob[(size_t)c * N + nn] = sout[c][nn];
    }
}

// ---------------------------------------------------------------------------
extern "C" void kernel_launch(void* const* d_in, const int* in_sizes, int n_in,
                              void* d_out, int out_size)
{
    const float* xyz   = (const float*)d_in[0];
    const float* x     = (const float*)d_in[1];
    const float* W     = (const float*)d_in[2];
    const float* gamma = (const float*)d_in[3];
    const float* beta  = (const float*)d_in[4];
    const float* rmean = (const float*)d_in[5];
    const float* rvar  = (const float*)d_in[6];
    float* out = (float*)d_out;

    prep_kernel<<<B * N / 256, 256>>>(xyz);
    gemm_bn_relu_kernel<<<dim3(N / 64, B), 256>>>(x, W, gamma, beta, rmean, rvar);
    knn_kernel<<<dim3(N / 32, B), 128>>>();
    gather_kernel<<<dim3(N / 32, B), 256>>>(out);
}

// round 9
// speedup vs baseline: 1.7047x; 1.0496x over previous
#include <cuda_runtime.h>
#include <cuda_bf16.h>
#include <cuda_fp16.h>
#include <math_constants.h>

#define FULL 0xffffffffu

static constexpr int B = 8;
static constexpr int N = 4096;
static constexpr int C = 128;
static constexpr int KNN = 16;

// scratch (device globals: no allocation allowed)
__device__ __half g_zbn[B * N * C];    // zbn[b][n][c] fp16, n-major rows 256B
__device__ float4 g_xyz4[B * N];       // (x,y,z,|p|^2)
__device__ int    g_idx[B * N * KNN];  // 16 NN indices per query

// ---------------------------------------------------------------------------
// Kernel 0: pack xyz + squared norm into float4
// ---------------------------------------------------------------------------
__global__ void prep_kernel(const float* __restrict__ xyz)
{
    int i = blockIdx.x * 256 + threadIdx.x;   // over B*N
    float x = xyz[3 * i], y = xyz[3 * i + 1], z = xyz[3 * i + 2];
    g_xyz4[i] = make_float4(x, y, z, x * x + y * y + z * z);
}

// ---------------------------------------------------------------------------
// Kernel 1: zbn[b][n][c] = relu(scale_c * (sum_k W[c][k] * x[b][k][n]) + bias_c)
// fp32 math, fp16 store.
// ---------------------------------------------------------------------------
__global__ __launch_bounds__(256) void gemm_bn_relu_kernel(
    const float* __restrict__ x,      // [B][C][N]
    const float* __restrict__ W,      // [C_out][C_in]
    const float* __restrict__ gamma,
    const float* __restrict__ beta,
    const float* __restrict__ rmean,
    const float* __restrict__ rvar)
{
    __shared__ float xs[32][64];    // [k][n]
    __shared__ float ws[32][128];   // [k][c], XOR-swizzled in 4-float units

    const int b  = blockIdx.y;
    const int n0 = blockIdx.x * 64;
    const int tid = threadIdx.x;
    const int tc = tid & 31;
    const int tn = tid >> 5;

    float acc[4][8];
#pragma unroll
    for (int j = 0; j < 4; ++j)
#pragma unroll
        for (int i = 0; i < 8; ++i) acc[j][i] = 0.0f;

    const float* xb = x + (size_t)b * C * N;

    for (int k0 = 0; k0 < C; k0 += 32) {
#pragma unroll
        for (int i = tid; i < 32 * 64; i += 256) {
            int kk = i >> 6, nn = i & 63;
            xs[kk][nn] = xb[(size_t)(k0 + kk) * N + n0 + nn];
        }
#pragma unroll
        for (int i = tid; i < 32 * 128; i += 256) {
            int c = i >> 5, kk = i & 31;
            ws[kk][c ^ ((kk & 7) << 2)] = W[c * C + k0 + kk];
        }
        __syncthreads();

#pragma unroll
        for (int kk = 0; kk < 32; ++kk) {
            float4 wv  = *(const float4*)&ws[kk][((tc ^ (kk & 7)) << 2)];
            float4 xv0 = *(const float4*)&xs[kk][tn * 8];
            float4 xv1 = *(const float4*)&xs[kk][tn * 8 + 4];
            float wj[4] = {wv.x, wv.y, wv.z, wv.w};
            float xi[8] = {xv0.x, xv0.y, xv0.z, xv0.w, xv1.x, xv1.y, xv1.z, xv1.w};
#pragma unroll
            for (int j = 0; j < 4; ++j)
#pragma unroll
                for (int i = 0; i < 8; ++i)
                    acc[j][i] = fmaf(wj[j], xi[i], acc[j][i]);
        }
        __syncthreads();
    }

    const int c0 = tc * 4;
    float sc[4], bi[4];
#pragma unroll
    for (int j = 0; j < 4; ++j) {
        sc[j] = gamma[c0 + j] * rsqrtf(rvar[c0 + j] + 1e-5f);
        bi[j] = beta[c0 + j] - rmean[c0 + j] * sc[j];
    }
#pragma unroll
    for (int i = 0; i < 8; ++i) {
        int n = n0 + tn * 8 + i;
        float ox = fmaxf(fmaf(acc[0][i], sc[0], bi[0]), 0.0f);
        float oy = fmaxf(fmaf(acc[1][i], sc[1], bi[1]), 0.0f);
        float oz = fmaxf(fmaf(acc[2][i], sc[2], bi[2]), 0.0f);
        float ow = fmaxf(fmaf(acc[3][i], sc[3], bi[3]), 0.0f);
        __half2 h01 = __floats2half2_rn(ox, oy);
        __half2 h23 = __floats2half2_rn(oz, ow);
        uint2 u;
        u.x = *reinterpret_cast<unsigned*>(&h01);
        u.y = *reinterpret_cast<unsigned*>(&h23);
        *(uint2*)&g_zbn[((size_t)b * N + n) * C + c0] = u;
    }
}

// ---------------------------------------------------------------------------
// Kernel 2: top-16 KNN, thread-per-(query,split), 4 splits of 1024 candidates.
// 256-thread block = 64 queries x 4 splits (each warp homogeneous in split).
// Candidates staged through smem tiles; inner loop is two-phase:
//   A) compute 8 distances (independent LDS+FLOP chains, loads pipelined)
//   B) 8 branch-free accept sequences (setp + predicated STS + add)
// This removes the per-candidate asm memory-clobber serialization of R8 while
// keeping candidate order / flush points / merge bit-identical.
// Grid: (N/64, B) = 512 blocks.
// ---------------------------------------------------------------------------
__device__ __forceinline__ void insert16(float (&tv)[16], int (&ti)[16],
                                         float e, int jj)
{
#pragma unroll
    for (int t = 15; t >= 0; --t) {
        bool gt  = tv[t] > e;                   // strict: ties keep incumbent
        bool gtp = (t > 0) && (tv[t - 1] > e);
        float nv = gtp ? tv[t - 1] : e;
        int   ni = gtp ? ti[t - 1] : jj;
        if (gt) { tv[t] = nv; ti[t] = ni; }
    }
}

__global__ __launch_bounds__(256) void knn_kernel()
{
    __shared__ unsigned long long buf[16][256];  // accept buffer, 32KB
    __shared__ float4 tile[1024];                // 4 chunks x 256 points, 16KB
    __shared__ float sthr[64][5];                // per-query split thresholds

    const int tid  = threadIdx.x;
    const int u    = tid & 63;                   // query slot in block
    const int s    = tid >> 6;                   // split 0..3 (warp-homogeneous)
    const int b    = blockIdx.y;
    const int q    = blockIdx.x * 64 + u;

    // init shared thresholds
    for (int i = tid; i < 64 * 5; i += 256) ((float*)sthr)[i] = CUDART_INF_F;

    const float4* __restrict__ xb = g_xyz4 + (size_t)b * N;
    const float4 Q = __ldg(&xb[q]);
    const float qs = Q.w;

    float tv[16]; int ti[16];
#pragma unroll
    for (int t = 0; t < 16; ++t) { tv[t] = CUDART_INF_F; ti[t] = 0; }

    const int lo = s << 10;                      // s * 1024
    const float4* __restrict__ mychunk = tile + (s << 8);

    unsigned addr0 = (unsigned)__cvta_generic_to_shared(&buf[0][0]) + tid * 8u;
    unsigned addr  = addr0;
    const unsigned athr = addr0 + 8u * 2048u;    // trigger: cnt >= 8 (stride 2048)
    float fthr = CUDART_INF_F;

#define KNN_FLUSH() do {                                                      \
        int cnt = (int)((addr - addr0) >> 11);                                \
        int mx  = __reduce_max_sync(FULL, cnt);                               \
        for (int t = 0; t < mx; ++t) {                                        \
            unsigned long long e = buf[t][tid];                               \
            float ed = (t < cnt) ? __uint_as_float((unsigned)(e >> 32))       \
                                 : CUDART_INF_F;                              \
            int   ej = (int)(unsigned)e;                                      \
            insert16(tv, ti, ed, ej);                                         \
        }                                                                     \
        addr = addr0;                                                         \
        sthr[u][s] = tv[15];                                                  \
        fthr = fminf(fminf(sthr[u][0], sthr[u][1]),                           \
                     fminf(sthr[u][2], sthr[u][3]));                          \
    } while (0)

#pragma unroll 1
    for (int it = 0; it < 4; ++it) {
        // ---- stage 4x256 chunk tile (coalesced; barrier protects reads) ----
        __syncthreads();
#pragma unroll
        for (int k = 0; k < 4; ++k) {
            int flat = tid + (k << 8);           // 0..1023
            int ch = flat >> 8, off = flat & 255;
            tile[flat] = __ldg(&xb[(ch << 10) + (it << 8) + off]);
        }
        __syncthreads();

        const int jbase = lo + (it << 8);
        int t0 = 0;

        if (it == 0) {
            // ---- seed: first 16 candidates of own range, co-executed inserts ----
#pragma unroll 1
            for (int jj = 0; jj < 16; ++jj) {
                float4 p = mychunk[jj];
                float dot = Q.x * p.x;
                dot = fmaf(Q.y, p.y, dot);
                dot = fmaf(Q.z, p.z, dot);
                float d = fmaf(-2.0f, dot, qs + p.w);
                insert16(tv, ti, d, jbase + jj);
            }
            sthr[u][s] = tv[15];
            fthr = fminf(fminf(sthr[u][0], sthr[u][1]),
                         fminf(sthr[u][2], sthr[u][3]));
            t0 = 16;
        }

        // ---- scan chunk: phase A distances, phase B accepts ----
#pragma unroll 1
        for (; t0 < 256; t0 += 8) {
            float d[8];
#pragma unroll
            for (int uu = 0; uu < 8; ++uu) {
                float4 p = mychunk[t0 + uu];
                float dot = Q.x * p.x;
                dot = fmaf(Q.y, p.y, dot);
                dot = fmaf(Q.z, p.z, dot);
                d[uu] = fmaf(-2.0f, dot, qs + p.w);
            }
#pragma unroll
            for (int uu = 0; uu < 8; ++uu) {
                int j = jbase + t0 + uu;
                unsigned db = __float_as_uint(d[uu]);
                asm volatile(
                    "{\n\t"
                    ".reg .pred p;\n\t"
                    "setp.lt.f32 p, %1, %2;\n\t"
                    "@p st.shared.v2.b32 [%0], {%3, %4};\n\t"
                    "@p add.u32 %0, %0, 2048;\n\t"
                    "}"
                    : "+r"(addr) : "f"(d[uu]), "f"(fthr), "r"(j), "r"(db) : "memory");
            }
            if (__any_sync(FULL, addr >= athr)) KNN_FLUSH();
        }
    }
    // ---- final flush ----
    if (__any_sync(FULL, addr != addr0)) KNN_FLUSH();
#undef KNN_FLUSH

    // ---- merge splits 1..3 into split 0 (ascending split order preserves
    //      lower-index-on-tie). Staging overlays the dead accept buffer. ----
    __syncthreads();                             // all flush reads of buf done
    float (*mD)[3][17] = (float(*)[3][17])&buf[0][0];
    int   (*mI)[3][17] = (int(*)[3][17])((float*)&buf[0][0] + 64 * 3 * 17);

    if (s != 0) {
#pragma unroll
        for (int t = 0; t < 16; ++t) {
            mD[u][s - 1][t] = tv[t];
            mI[u][s - 1][t] = ti[t];
        }
    }
    __syncthreads();
    if (s == 0) {
#pragma unroll 1
        for (int k = 0; k < 3; ++k)
#pragma unroll 1
            for (int t = 0; t < 16; ++t)
                insert16(tv, ti, mD[u][k][t], mI[u][k][t]);

        int* op = g_idx + ((size_t)b * N + q) * KNN;
#pragma unroll
        for (int t = 0; t < 16; ++t) op[t] = ti[t];
    }
}

// ---------------------------------------------------------------------------
// Kernel 3: gather-max over 16 neighbors (fp16 rows, one LDG.64 + 2 HMNMX2
// per row per lane) + transpose to [B][C][N] float.
// Warp per query (4 queries/warp), 256 threads. Grid: (N/32, B).
// ---------------------------------------------------------------------------
__global__ __launch_bounds__(256) void gather_kernel(float* __restrict__ out)
{
    __shared__ float sout[128][33];

    const int b    = blockIdx.y;
    const int n0   = blockIdx.x * 32;
    const int tid  = threadIdx.x;
    const int w    = tid >> 5;
    const int lane = tid & 31;

    const __half* __restrict__ zb = g_zbn + (size_t)b * N * C;

    for (int s = 0; s < 4; ++s) {
        const int ql = w * 4 + s;
        const int n  = n0 + ql;
        int myidx = (lane < 16) ? g_idx[((size_t)b * N + n) * KNN + lane] : 0;

        __half2 m01 = __float2half2_rn(0.0f);   // post-ReLU >= 0
        __half2 m23 = __float2half2_rn(0.0f);
#pragma unroll
        for (int t = 0; t < KNN; t += 2) {
            int j1 = __shfl_sync(FULL, myidx, t);
            int j2 = __shfl_sync(FULL, myidx, t + 1);
            const uint2* r1 = (const uint2*)(zb + ((size_t)j1 << 7));
            const uint2* r2 = (const uint2*)(zb + ((size_t)j2 << 7));
            uint2 u1 = __ldg(&r1[lane]);
            uint2 u2 = __ldg(&r2[lane]);
            m01 = __hmax2(m01, *reinterpret_cast<__half2*>(&u1.x));
            m23 = __hmax2(m23, *reinterpret_cast<__half2*>(&u1.y));
            m01 = __hmax2(m01, *reinterpret_cast<__half2*>(&u2.x));
            m23 = __hmax2(m23, *reinterpret_cast<__half2*>(&u2.y));
        }

        float2 f01 = __half22float2(m01);
        float2 f23 = __half22float2(m23);
        sout[4 * lane + 0][ql] = f01.x;
        sout[4 * lane + 1][ql] = f01.y;
        sout[4 * lane + 2][ql] = f23.x;
        sout[4 * lane + 3][ql] = f23.y;
    }
    __syncthreads();

    float* ob = out + (size_t)b * C * N + n0;
    for (int i = tid; i < 128 * 32; i += 256) {
        int c = i >> 5, nn = i & 31;
        ob[(size_t)c * N + nn] = sout[c][nn];
    }
}

// ---------------------------------------------------------------------------
extern "C" void kernel_launch(void* const* d_in, const int* in_sizes, int n_in,
                              void* d_out, int out_size)
{
    const float* xyz   = (const float*)d_in[0];
    const float* x     = (const float*)d_in[1];
    const float* W     = (const float*)d_in[2];
    const float* gamma = (const float*)d_in[3];
    const float* beta  = (const float*)d_in[4];
    const float* rmean = (const float*)d_in[5];
    const float* rvar  = (const float*)d_in[6];
    float* out = (float*)d_out;

    prep_kernel<<<B * N / 256, 256>>>(xyz);
    gemm_bn_relu_kernel<<<dim3(N / 64, B), 256>>>(x, W, gamma, beta, rmean, rvar);
    knn_kernel<<<dim3(N / 64, B), 256>>>();
    gather_kernel<<<dim3(N / 32, B), 256>>>(out);
}